// round 15
// baseline (speedup 1.0000x reference)
#include <cuda_runtime.h>

#define NTOK 8192
#define DIM 128
#define ODIM 128
#define THREADS 64
#define OT 4
#define TOKPT 4

typedef unsigned long long u64;

__device__ float g_xnT[DIM * NTOK];   // transposed: [d][n]
__device__ float2 g_musv[NTOK];
__device__ float g_T [ODIM * DIM];
__device__ float g_A [ODIM * DIM];
__device__ float g_CP[ODIM * DIM];
__device__ float g_W [ODIM * DIM];
__device__ float g_K1[ODIM], g_K2[ODIM];

__device__ __forceinline__ float2 ffma2(float2 a, float2 b, float2 c) {
    float2 d;
    asm("fma.rn.f32x2 %0, %1, %2, %3;"
        : "=l"(reinterpret_cast<u64&>(d))
        : "l"(reinterpret_cast<u64 const&>(a)),
          "l"(reinterpret_cast<u64 const&>(b)),
          "l"(reinterpret_cast<u64 const&>(c)));
    return d;
}
__device__ __forceinline__ float2 fmul2(float2 a, float2 b) {
    float2 d;
    asm("mul.rn.f32x2 %0, %1, %2;"
        : "=l"(reinterpret_cast<u64&>(d))
        : "l"(reinterpret_cast<u64 const&>(a)),
          "l"(reinterpret_cast<u64 const&>(b)));
    return d;
}
__device__ __forceinline__ float2 fadd2(float2 a, float2 b) {
    float2 d;
    asm("add.rn.f32x2 %0, %1, %2;"
        : "=l"(reinterpret_cast<u64&>(d))
        : "l"(reinterpret_cast<u64 const&>(a)),
          "l"(reinterpret_cast<u64 const&>(b)));
    return d;
}
__device__ __forceinline__ float ex2f(float a) {
    float r; asm("ex2.approx.ftz.f32 %0, %1;" : "=f"(r) : "f"(a)); return r;
}

// ---------------- Kernel 0: param fold + K1/K2 (block per o) ----------------
__global__ void prep_kernel(const float* __restrict__ scale,
                            const float* __restrict__ trans,
                            const float* __restrict__ ww,
                            const float* __restrict__ bw,
                            const float* __restrict__ gamma,
                            const float* __restrict__ beta) {
    const int o = blockIdx.x;
    const int d = threadIdx.x;       // 128 threads
    const int gi = o * DIM + d;
    const float H = 0.72134752f;

    float sc = scale[gi];
    float sp = (sc > 20.0f) ? sc : log1pf(expf(sc));
    float s = sp + 0.1f;
    float wprime = bw[gi] / gamma[d];
    g_T [gi] = -trans[gi];
    g_A [gi] = -H / (s * s);
    g_CP[gi] = -0.7292730f * ww[gi];
    g_W [gi] = wprime;

    // block reduce K1 = sum beta*W', K2 = sum bw
    __shared__ float r1[4], r2[4];
    float k1 = wprime * beta[d];
    float k2 = bw[gi];
    #pragma unroll
    for (int off = 16; off; off >>= 1) {
        k1 += __shfl_xor_sync(~0u, k1, off);
        k2 += __shfl_xor_sync(~0u, k2, off);
    }
    int w = d >> 5, lane = d & 31;
    if (lane == 0) { r1[w] = k1; r2[w] = k2; }
    __syncthreads();
    if (d == 0) {
        g_K1[o] = r1[0] + r1[1] + r1[2] + r1[3];
        g_K2[o] = r2[0] + r2[1] + r2[2] + r2[3];
    }
}

// ---------------- Kernel 1: LayerNorm + transpose (warp per token) ----------------
__global__ void ln_kernel(const float* __restrict__ x,
                          const float* __restrict__ gamma,
                          const float* __restrict__ beta) {
    __shared__ float sX[8][DIM];
    const int tok0 = blockIdx.x * 8;
    const int w = threadIdx.x >> 5;
    const int lane = threadIdx.x & 31;
    const int token = tok0 + w;

    float4 v = ((const float4*)(x + (size_t)token * DIM))[lane];
    float s = (v.x + v.y) + (v.z + v.w);
    #pragma unroll
    for (int off = 16; off; off >>= 1) s += __shfl_xor_sync(~0u, s, off);
    float mu = s * (1.0f / DIM);
    float dx = v.x - mu, dy = v.y - mu, dz = v.z - mu, dw = v.w - mu;
    float q = (dx * dx + dy * dy) + (dz * dz + dw * dw);
    #pragma unroll
    for (int off = 16; off; off >>= 1) q += __shfl_xor_sync(~0u, q, off);
    float ve = q * (1.0f / DIM) + 1e-5f;
    float r = rsqrtf(ve);
    float4 g = ((const float4*)gamma)[lane];
    float4 b = ((const float4*)beta)[lane];
    float4 o;
    o.x = fmaf(dx * r, g.x, b.x);
    o.y = fmaf(dy * r, g.y, b.y);
    o.z = fmaf(dz * r, g.z, b.z);
    o.w = fmaf(dw * r, g.w, b.w);
    ((float4*)&sX[w][0])[lane] = o;
    if (lane == 0) g_musv[token] = make_float2(mu, ve * r);
    __syncthreads();

    const int d = threadIdx.x >> 1;
    const int h = threadIdx.x & 1;
    float4 val;
    val.x = sX[4 * h + 0][d];
    val.y = sX[4 * h + 1][d];
    val.z = sX[4 * h + 2][d];
    val.w = sX[4 * h + 3][d];
    *((float4*)(g_xnT + (size_t)d * NTOK + tok0 + 4 * h)) = val;
}

// ---------------- Kernel 2: wavelet + base, 64-thread CTAs, prefetch ----------------
__global__ __launch_bounds__(THREADS, 8)
void wave_kernel(float* __restrict__ out) {
    __shared__ float4 sT [OT][DIM / 4];
    __shared__ float4 sA [OT][DIM / 4];
    __shared__ float4 sCP[OT][DIM / 4];
    __shared__ float4 sW [OT][DIM / 4];
    __shared__ float  sK1[OT], sK2[OT];

    const int o0 = blockIdx.y * OT;
    const int tid = threadIdx.x;
    const float H = 0.72134752f;
    const float2 H2 = make_float2(H, H);

    // ---- pure copy prologue: 4 arrays x 128 float4 each ----
    #pragma unroll
    for (int k = 0; k < (OT * DIM / 4) / THREADS; k++) {   // 2 iters
        int i = tid + k * THREADS;                          // float4 idx < 128
        ((float4*)sT)[i]  = ((const float4*)(g_T  + o0 * DIM))[i];
        ((float4*)sA)[i]  = ((const float4*)(g_A  + o0 * DIM))[i];
        ((float4*)sCP)[i] = ((const float4*)(g_CP + o0 * DIM))[i];
        ((float4*)sW)[i]  = ((const float4*)(g_W  + o0 * DIM))[i];
    }
    if (tid < OT) {
        sK1[tid] = g_K1[o0 + tid];
        sK2[tid] = g_K2[o0 + tid];
    }
    __syncthreads();

    const int n0 = blockIdx.x * (THREADS * TOKPT) + tid;  // token t at n0 + t*THREADS
    const float* xT = g_xnT + n0;

    float2 accw[OT][TOKPT], accb[OT][TOKPT];
    #pragma unroll
    for (int o = 0; o < OT; o++)
        #pragma unroll
        for (int t = 0; t < TOKPT; t++) {
            accw[o][t] = make_float2(0.0f, 0.0f);
            accb[o][t] = make_float2(0.0f, 0.0f);
        }

    // double-buffered x registers
    float2 xp[2][TOKPT][2];
    #pragma unroll
    for (int t = 0; t < TOKPT; t++) {
        const float* pt = xT + t * THREADS;
        xp[0][t][0] = make_float2(pt[0],        pt[NTOK]);
        xp[0][t][1] = make_float2(pt[2 * NTOK], pt[3 * NTOK]);
    }

    #pragma unroll 2
    for (int dc = 0; dc < DIM / 4; dc++) {
        const int cur = dc & 1, nxt = cur ^ 1;
        {
            const float* pn = xT + (size_t)(4 * ((dc + 1) & (DIM / 4 - 1))) * NTOK;
            #pragma unroll
            for (int t = 0; t < TOKPT; t++) {
                const float* pt = pn + t * THREADS;
                xp[nxt][t][0] = make_float2(pt[0],        pt[NTOK]);
                xp[nxt][t][1] = make_float2(pt[2 * NTOK], pt[3 * NTOK]);
            }
        }

        #pragma unroll
        for (int o = 0; o < OT; o++) {
            float4 T4 = sT [o][dc];
            float4 A4 = sA [o][dc];
            float4 P4 = sCP[o][dc];
            float4 W4 = sW [o][dc];
            float2 Tl = make_float2(T4.x, T4.y), Th = make_float2(T4.z, T4.w);
            float2 Al = make_float2(A4.x, A4.y), Ah = make_float2(A4.z, A4.w);
            float2 Pl = make_float2(P4.x, P4.y), Ph = make_float2(P4.z, P4.w);
            float2 Wl = make_float2(W4.x, W4.y), Wh = make_float2(W4.z, W4.w);
            #pragma unroll
            for (int t = 0; t < TOKPT; t++) {
                {
                    float2 y = fadd2(xp[cur][t][0], Tl);
                    float2 q = fmul2(y, y);
                    float2 m = ffma2(q, Al, H2);
                    float2 e = make_float2(ex2f(m.x), ex2f(m.y));
                    float2 g = fmul2(m, e);
                    accw[o][t] = ffma2(g, Pl, accw[o][t]);
                }
                {
                    float2 y = fadd2(xp[cur][t][1], Th);
                    float2 q = fmul2(y, y);
                    float2 m = ffma2(q, Ah, H2);
                    float2 e = make_float2(ex2f(m.x), ex2f(m.y));
                    float2 g = fmul2(m, e);
                    accw[o][t] = ffma2(g, Ph, accw[o][t]);
                }
                accb[o][t] = ffma2(xp[cur][t][0], Wl, accb[o][t]);
                accb[o][t] = ffma2(xp[cur][t][1], Wh, accb[o][t]);
            }
        }
    }

    // ---- epilogue ----
    #pragma unroll
    for (int t = 0; t < TOKPT; t++) {
        int n = n0 + t * THREADS;
        float2 ms = g_musv[n];
        float* op = out + (size_t)n * ODIM + o0;
        float4 res;
        float* rp = (float*)&res;
        #pragma unroll
        for (int j = 0; j < 4; j++) {
            float ac = accb[j][t].x + accb[j][t].y;
            float b = fmaf(ms.y, ac - sK1[j], ms.x * sK2[j]);
            float e = ex2f(-1.44269504f * b);
            float sig = __frcp_rn(1.0f + e);
            rp[j] = fmaf(b, sig, accw[j][t].x + accw[j][t].y);
        }
        ((float4*)op)[0] = res;
    }
}

extern "C" void kernel_launch(void* const* d_in, const int* in_sizes, int n_in,
                              void* d_out, int out_size) {
    const float* x     = (const float*)d_in[0];
    const float* scale = (const float*)d_in[1];
    const float* trans = (const float*)d_in[2];
    const float* ww    = (const float*)d_in[3];
    const float* bw    = (const float*)d_in[4];
    const float* gamma = (const float*)d_in[5];
    const float* beta  = (const float*)d_in[6];
    float* out = (float*)d_out;

    prep_kernel<<<ODIM, DIM>>>(scale, trans, ww, bw, gamma, beta);
    ln_kernel<<<NTOK / 8, 256>>>(x, gamma, beta);
    dim3 grid(NTOK / (THREADS * TOKPT), ODIM / OT);
    wave_kernel<<<grid, THREADS>>>(out);
}

// round 16
// speedup vs baseline: 1.0045x; 1.0045x over previous
#include <cuda_runtime.h>
#include <cuda_fp16.h>

#define NTOK 8192
#define DIM 128
#define ODIM 128
#define THREADS 64
#define OT 4
#define TOKPT 4

typedef unsigned long long u64;
typedef unsigned int u32;

__device__ float g_xnT[DIM * NTOK];   // transposed: [d][n]
__device__ float2 g_musv[NTOK];
__device__ float g_T [ODIM * DIM];
__device__ float g_A [ODIM * DIM];
__device__ float g_W [ODIM * DIM];
__device__ u32   g_CPh[ODIM * DIM / 2];   // CP packed half2 per d-pair
__device__ float g_K1[ODIM], g_K2[ODIM];

__device__ __forceinline__ float2 ffma2(float2 a, float2 b, float2 c) {
    float2 d;
    asm("fma.rn.f32x2 %0, %1, %2, %3;"
        : "=l"(reinterpret_cast<u64&>(d))
        : "l"(reinterpret_cast<u64 const&>(a)),
          "l"(reinterpret_cast<u64 const&>(b)),
          "l"(reinterpret_cast<u64 const&>(c)));
    return d;
}
__device__ __forceinline__ float2 fmul2(float2 a, float2 b) {
    float2 d;
    asm("mul.rn.f32x2 %0, %1, %2;"
        : "=l"(reinterpret_cast<u64&>(d))
        : "l"(reinterpret_cast<u64 const&>(a)),
          "l"(reinterpret_cast<u64 const&>(b)));
    return d;
}
__device__ __forceinline__ float2 fadd2(float2 a, float2 b) {
    float2 d;
    asm("add.rn.f32x2 %0, %1, %2;"
        : "=l"(reinterpret_cast<u64&>(d))
        : "l"(reinterpret_cast<u64 const&>(a)),
          "l"(reinterpret_cast<u64 const&>(b)));
    return d;
}
__device__ __forceinline__ float ex2f(float a) {
    float r; asm("ex2.approx.ftz.f32 %0, %1;" : "=f"(r) : "f"(a)); return r;
}
__device__ __forceinline__ u32 pack2(float lo, float hi) {
    u32 r;
    asm("cvt.rn.f16x2.f32 %0, %1, %2;" : "=r"(r) : "f"(hi), "f"(lo));
    return r;
}
__device__ __forceinline__ u32 ex2h2(u32 a) {
    u32 r; asm("ex2.approx.f16x2 %0, %1;" : "=r"(r) : "r"(a)); return r;
}
__device__ __forceinline__ u32 hmul2(u32 a, u32 b) {
    u32 r; asm("mul.rn.f16x2 %0, %1, %2;" : "=r"(r) : "r"(a), "r"(b)); return r;
}
__device__ __forceinline__ u32 hfma2(u32 a, u32 b, u32 c) {
    u32 r; asm("fma.rn.f16x2 %0, %1, %2, %3;" : "=r"(r) : "r"(a), "r"(b), "r"(c));
    return r;
}

// ---------------- Kernel 1: LayerNorm + transpose; blocks<128 also fold params ----------------
__global__ void ln_kernel(const float* __restrict__ x,
                          const float* __restrict__ gamma,
                          const float* __restrict__ beta,
                          const float* __restrict__ scale,
                          const float* __restrict__ trans,
                          const float* __restrict__ ww,
                          const float* __restrict__ bw) {
    __shared__ float sX[8][DIM];
    const int tok0 = blockIdx.x * 8;
    const int w = threadIdx.x >> 5;
    const int lane = threadIdx.x & 31;
    const int token = tok0 + w;

    float4 v = ((const float4*)(x + (size_t)token * DIM))[lane];
    float s = (v.x + v.y) + (v.z + v.w);
    #pragma unroll
    for (int off = 16; off; off >>= 1) s += __shfl_xor_sync(~0u, s, off);
    float mu = s * (1.0f / DIM);
    float dx = v.x - mu, dy = v.y - mu, dz = v.z - mu, dw = v.w - mu;
    float q = (dx * dx + dy * dy) + (dz * dz + dw * dw);
    #pragma unroll
    for (int off = 16; off; off >>= 1) q += __shfl_xor_sync(~0u, q, off);
    float ve = q * (1.0f / DIM) + 1e-5f;
    float r = rsqrtf(ve);
    float4 g = ((const float4*)gamma)[lane];
    float4 b = ((const float4*)beta)[lane];
    float4 o;
    o.x = fmaf(dx * r, g.x, b.x);
    o.y = fmaf(dy * r, g.y, b.y);
    o.z = fmaf(dz * r, g.z, b.z);
    o.w = fmaf(dw * r, g.w, b.w);
    ((float4*)&sX[w][0])[lane] = o;
    if (lane == 0) g_musv[token] = make_float2(mu, ve * r);
    __syncthreads();

    {
        const int d = threadIdx.x >> 1;
        const int h = threadIdx.x & 1;
        float4 val;
        val.x = sX[4 * h + 0][d];
        val.y = sX[4 * h + 1][d];
        val.z = sX[4 * h + 2][d];
        val.w = sX[4 * h + 3][d];
        *((float4*)(g_xnT + (size_t)d * NTOK + tok0 + 4 * h)) = val;
    }

    // ---- param fold: block b < ODIM handles o = b (threads 0..127) ----
    if (blockIdx.x < ODIM && threadIdx.x < DIM) {
        const int oo = blockIdx.x;
        const int d = threadIdx.x;
        const int gi = oo * DIM + d;
        const float H = 0.72134752f;
        float sc = scale[gi];
        float sp = (sc > 20.0f) ? sc : log1pf(expf(sc));
        float ss = sp + 0.1f;
        float wprime = bw[gi] / gamma[d];
        g_T[gi] = -trans[gi];
        g_A[gi] = -H / (ss * ss);
        g_W[gi] = wprime;
        if (d < DIM / 2)
            g_CPh[oo * (DIM / 2) + d] =
                pack2(-0.7292730f * ww[oo * DIM + 2 * d],
                      -0.7292730f * ww[oo * DIM + 2 * d + 1]);

        // K1 = sum beta*W', K2 = sum bw  (warp reduce + smem combine)
        __shared__ float r1[4], r2[4];
        float k1 = wprime * beta[d];
        float k2 = bw[gi];
        #pragma unroll
        for (int off = 16; off; off >>= 1) {
            k1 += __shfl_xor_sync(~0u, k1, off);
            k2 += __shfl_xor_sync(~0u, k2, off);
        }
        int ww_ = d >> 5, lane_ = d & 31;
        if (lane_ == 0) { r1[ww_] = k1; r2[ww_] = k2; }
        __syncthreads();
        if (d == 0) {
            g_K1[oo] = r1[0] + r1[1] + r1[2] + r1[3];
            g_K2[oo] = r2[0] + r2[1] + r2[2] + r2[3];
        }
    }
}

// ---------------- Kernel 2: wavelet + base, 64-thr CTAs, prefetch, f16x2 exp ----------------
// T-form: y = xn + T, m = H + a*y^2 (f32) ; term = CP*m*2^m in f16x2
__global__ __launch_bounds__(THREADS, 8)
void wave_kernel(float* __restrict__ out) {
    __shared__ float4 sT[OT][DIM / 4];
    __shared__ float4 sA[OT][DIM / 4];
    __shared__ float4 sW[OT][DIM / 4];
    __shared__ uint2  sCPh[OT][DIM / 4];
    __shared__ float  sK1[OT], sK2[OT];

    const int o0 = blockIdx.y * OT;
    const int tid = threadIdx.x;
    const float H = 0.72134752f;
    const float2 H2 = make_float2(H, H);

    // ---- copy prologue ----
    #pragma unroll
    for (int k = 0; k < (OT * DIM / 4) / THREADS; k++) {   // 2 iters
        int i = tid + k * THREADS;
        ((float4*)sT)[i] = ((const float4*)(g_T + o0 * DIM))[i];
        ((float4*)sA)[i] = ((const float4*)(g_A + o0 * DIM))[i];
        ((float4*)sW)[i] = ((const float4*)(g_W + o0 * DIM))[i];
    }
    ((uint4*)sCPh)[tid] = ((const uint4*)(g_CPh + o0 * (DIM / 2)))[tid]; // 64 uint4
    if (tid < OT) {
        sK1[tid] = g_K1[o0 + tid];
        sK2[tid] = g_K2[o0 + tid];
    }
    __syncthreads();

    const int n0 = blockIdx.x * (THREADS * TOKPT) + tid;
    const float* xT = g_xnT + n0;

    float2 accw[OT][TOKPT], accb[OT][TOKPT];
    u32 acch[OT][TOKPT];
    #pragma unroll
    for (int o = 0; o < OT; o++)
        #pragma unroll
        for (int t = 0; t < TOKPT; t++) {
            accw[o][t] = make_float2(0.0f, 0.0f);
            accb[o][t] = make_float2(0.0f, 0.0f);
            acch[o][t] = 0u;
        }

    float2 xp[2][TOKPT][2];
    #pragma unroll
    for (int t = 0; t < TOKPT; t++) {
        const float* pt = xT + t * THREADS;
        xp[0][t][0] = make_float2(pt[0],        pt[NTOK]);
        xp[0][t][1] = make_float2(pt[2 * NTOK], pt[3 * NTOK]);
    }

    for (int dcb = 0; dcb < 8; dcb++) {
        #pragma unroll
        for (int dci = 0; dci < 4; dci++) {
            const int dc = dcb * 4 + dci;
            const int cur = dc & 1, nxt = cur ^ 1;
            {
                const float* pn = xT + (size_t)(4 * ((dc + 1) & (DIM / 4 - 1))) * NTOK;
                #pragma unroll
                for (int t = 0; t < TOKPT; t++) {
                    const float* pt = pn + t * THREADS;
                    xp[nxt][t][0] = make_float2(pt[0],        pt[NTOK]);
                    xp[nxt][t][1] = make_float2(pt[2 * NTOK], pt[3 * NTOK]);
                }
            }
            #pragma unroll
            for (int o = 0; o < OT; o++) {
                float4 T4 = sT[o][dc];
                float4 A4 = sA[o][dc];
                float4 W4 = sW[o][dc];
                uint2  C2 = sCPh[o][dc];
                float2 Tl = make_float2(T4.x, T4.y), Th = make_float2(T4.z, T4.w);
                float2 Al = make_float2(A4.x, A4.y), Ah = make_float2(A4.z, A4.w);
                float2 Wl = make_float2(W4.x, W4.y), Wh = make_float2(W4.z, W4.w);
                #pragma unroll
                for (int t = 0; t < TOKPT; t++) {
                    float2 y0 = fadd2(xp[cur][t][0], Tl);
                    float2 y1 = fadd2(xp[cur][t][1], Th);
                    float2 q0 = fmul2(y0, y0);
                    float2 q1 = fmul2(y1, y1);
                    float2 m0 = ffma2(q0, Al, H2);
                    float2 m1 = ffma2(q1, Ah, H2);
                    u32 mh0 = pack2(m0.x, m0.y);
                    u32 mh1 = pack2(m1.x, m1.y);
                    u32 e0 = ex2h2(mh0);
                    u32 e1 = ex2h2(mh1);
                    u32 g0 = hmul2(mh0, e0);
                    u32 g1 = hmul2(mh1, e1);
                    acch[o][t] = hfma2(g0, C2.x, acch[o][t]);
                    acch[o][t] = hfma2(g1, C2.y, acch[o][t]);
                    accb[o][t] = ffma2(xp[cur][t][0], Wl, accb[o][t]);
                    accb[o][t] = ffma2(xp[cur][t][1], Wh, accb[o][t]);
                }
            }
        }
        // flush h2 partials (8 terms each) into f32 accumulators
        #pragma unroll
        for (int o = 0; o < OT; o++)
            #pragma unroll
            for (int t = 0; t < TOKPT; t++) {
                __half2 hv = *reinterpret_cast<__half2*>(&acch[o][t]);
                float2 fv = __half22float2(hv);
                accw[o][t] = fadd2(fv, accw[o][t]);
                acch[o][t] = 0u;
            }
    }

    // ---- epilogue ----
    #pragma unroll
    for (int t = 0; t < TOKPT; t++) {
        int n = n0 + t * THREADS;
        float2 ms = g_musv[n];
        float* op = out + (size_t)n * ODIM + o0;
        float4 res;
        float* rp = (float*)&res;
        #pragma unroll
        for (int j = 0; j < 4; j++) {
            float ac = accb[j][t].x + accb[j][t].y;
            float b = fmaf(ms.y, ac - sK1[j], ms.x * sK2[j]);
            float e = ex2f(-1.44269504f * b);
            float sig = __frcp_rn(1.0f + e);
            rp[j] = fmaf(b, sig, accw[j][t].x + accw[j][t].y);
        }
        ((float4*)op)[0] = res;
    }
}

extern "C" void kernel_launch(void* const* d_in, const int* in_sizes, int n_in,
                              void* d_out, int out_size) {
    const float* x     = (const float*)d_in[0];
    const float* scale = (const float*)d_in[1];
    const float* trans = (const float*)d_in[2];
    const float* ww    = (const float*)d_in[3];
    const float* bw    = (const float*)d_in[4];
    const float* gamma = (const float*)d_in[5];
    const float* beta  = (const float*)d_in[6];
    float* out = (float*)d_out;

    ln_kernel<<<NTOK / 8, 256>>>(x, gamma, beta, scale, trans, ww, bw);
    dim3 grid(NTOK / (THREADS * TOKPT), ODIM / OT);
    wave_kernel<<<grid, THREADS>>>(out);
}

// round 17
// speedup vs baseline: 1.0484x; 1.0437x over previous
#include <cuda_runtime.h>

#define NTOK 8192
#define DIM 128
#define ODIM 128
#define THREADS 64
#define OT 4
#define TOKPT 4

typedef unsigned long long u64;

__device__ float g_xnT[DIM * NTOK];   // transposed: [d][n]
__device__ float2 g_musv[NTOK];
__device__ float g_T [ODIM * DIM];
__device__ float g_A [ODIM * DIM];
__device__ float g_CP[ODIM * DIM];
__device__ float g_W [ODIM * DIM];
__device__ float g_K1[ODIM], g_K2[ODIM];

__device__ __forceinline__ float2 ffma2(float2 a, float2 b, float2 c) {
    float2 d;
    asm("fma.rn.f32x2 %0, %1, %2, %3;"
        : "=l"(reinterpret_cast<u64&>(d))
        : "l"(reinterpret_cast<u64 const&>(a)),
          "l"(reinterpret_cast<u64 const&>(b)),
          "l"(reinterpret_cast<u64 const&>(c)));
    return d;
}
__device__ __forceinline__ float2 fmul2(float2 a, float2 b) {
    float2 d;
    asm("mul.rn.f32x2 %0, %1, %2;"
        : "=l"(reinterpret_cast<u64&>(d))
        : "l"(reinterpret_cast<u64 const&>(a)),
          "l"(reinterpret_cast<u64 const&>(b)));
    return d;
}
__device__ __forceinline__ float2 fadd2(float2 a, float2 b) {
    float2 d;
    asm("add.rn.f32x2 %0, %1, %2;"
        : "=l"(reinterpret_cast<u64&>(d))
        : "l"(reinterpret_cast<u64 const&>(a)),
          "l"(reinterpret_cast<u64 const&>(b)));
    return d;
}
__device__ __forceinline__ float ex2f(float a) {
    float r; asm("ex2.approx.ftz.f32 %0, %1;" : "=f"(r) : "f"(a)); return r;
}

// ---------------- Kernel 1: LayerNorm + transpose; blocks<128 also fold params ----------------
__global__ void ln_kernel(const float* __restrict__ x,
                          const float* __restrict__ gamma,
                          const float* __restrict__ beta,
                          const float* __restrict__ scale,
                          const float* __restrict__ trans,
                          const float* __restrict__ ww,
                          const float* __restrict__ bw) {
    __shared__ float sX[8][DIM];
    const int tok0 = blockIdx.x * 8;
    const int w = threadIdx.x >> 5;
    const int lane = threadIdx.x & 31;
    const int token = tok0 + w;

    float4 v = ((const float4*)(x + (size_t)token * DIM))[lane];
    float s = (v.x + v.y) + (v.z + v.w);
    #pragma unroll
    for (int off = 16; off; off >>= 1) s += __shfl_xor_sync(~0u, s, off);
    float mu = s * (1.0f / DIM);
    float dx = v.x - mu, dy = v.y - mu, dz = v.z - mu, dw = v.w - mu;
    float q = (dx * dx + dy * dy) + (dz * dz + dw * dw);
    #pragma unroll
    for (int off = 16; off; off >>= 1) q += __shfl_xor_sync(~0u, q, off);
    float ve = q * (1.0f / DIM) + 1e-5f;
    float r = rsqrtf(ve);
    float4 g = ((const float4*)gamma)[lane];
    float4 b = ((const float4*)beta)[lane];
    float4 o;
    o.x = fmaf(dx * r, g.x, b.x);
    o.y = fmaf(dy * r, g.y, b.y);
    o.z = fmaf(dz * r, g.z, b.z);
    o.w = fmaf(dw * r, g.w, b.w);
    ((float4*)&sX[w][0])[lane] = o;
    if (lane == 0) g_musv[token] = make_float2(mu, ve * r);
    __syncthreads();

    {
        const int d = threadIdx.x >> 1;
        const int h = threadIdx.x & 1;
        float4 val;
        val.x = sX[4 * h + 0][d];
        val.y = sX[4 * h + 1][d];
        val.z = sX[4 * h + 2][d];
        val.w = sX[4 * h + 3][d];
        *((float4*)(g_xnT + (size_t)d * NTOK + tok0 + 4 * h)) = val;
    }

    // ---- param fold: block b < ODIM handles o = b (threads 0..127) ----
    if (blockIdx.x < ODIM && threadIdx.x < DIM) {
        const int oo = blockIdx.x;
        const int d = threadIdx.x;
        const int gi = oo * DIM + d;
        const float H = 0.72134752f;
        float sc = scale[gi];
        float sp = (sc > 20.0f) ? sc : log1pf(expf(sc));
        float ss = sp + 0.1f;
        float wprime = bw[gi] / gamma[d];
        g_T [gi] = -trans[gi];
        g_A [gi] = -H / (ss * ss);
        g_CP[gi] = -0.7292730f * ww[gi];
        g_W [gi] = wprime;

        __shared__ float r1[4], r2[4];
        float k1 = wprime * beta[d];
        float k2 = bw[gi];
        #pragma unroll
        for (int off = 16; off; off >>= 1) {
            k1 += __shfl_xor_sync(~0u, k1, off);
            k2 += __shfl_xor_sync(~0u, k2, off);
        }
        int ww_ = d >> 5, lane_ = d & 31;
        if (lane_ == 0) { r1[ww_] = k1; r2[ww_] = k2; }
        __syncthreads();
        if (d == 0) {
            g_K1[oo] = r1[0] + r1[1] + r1[2] + r1[3];
            g_K2[oo] = r2[0] + r2[1] + r2[2] + r2[3];
        }
    }
}

// ---------------- Kernel 2: wavelet + base, 64-thr CTAs, prefetch, f32 EX2 ----------------
// T-form: y = xn + T (T=-t), m = H + a*y^2 (a=-H/s^2, H=1/(2 ln2))
//   contribution = CP * m * 2^m,  CP = -C*ww/(H*2^H) = -0.7292730*ww
// base in xn-domain: b_o = sv*(acc_o - K1_o) + mu*K2_o
__global__ __launch_bounds__(THREADS, 8)
void wave_kernel(float* __restrict__ out) {
    __shared__ float4 sT [OT][DIM / 4];
    __shared__ float4 sA [OT][DIM / 4];
    __shared__ float4 sCP[OT][DIM / 4];
    __shared__ float4 sW [OT][DIM / 4];
    __shared__ float  sK1[OT], sK2[OT];

    const int o0 = blockIdx.y * OT;
    const int tid = threadIdx.x;
    const float H = 0.72134752f;
    const float2 H2 = make_float2(H, H);

    // ---- pure copy prologue: 4 arrays x 128 float4 each ----
    #pragma unroll
    for (int k = 0; k < (OT * DIM / 4) / THREADS; k++) {   // 2 iters
        int i = tid + k * THREADS;                          // float4 idx < 128
        ((float4*)sT)[i]  = ((const float4*)(g_T  + o0 * DIM))[i];
        ((float4*)sA)[i]  = ((const float4*)(g_A  + o0 * DIM))[i];
        ((float4*)sCP)[i] = ((const float4*)(g_CP + o0 * DIM))[i];
        ((float4*)sW)[i]  = ((const float4*)(g_W  + o0 * DIM))[i];
    }
    if (tid < OT) {
        sK1[tid] = g_K1[o0 + tid];
        sK2[tid] = g_K2[o0 + tid];
    }
    __syncthreads();

    const int n0 = blockIdx.x * (THREADS * TOKPT) + tid;  // token t at n0 + t*THREADS
    const float* xT = g_xnT + n0;

    float2 accw[OT][TOKPT], accb[OT][TOKPT];
    #pragma unroll
    for (int o = 0; o < OT; o++)
        #pragma unroll
        for (int t = 0; t < TOKPT; t++) {
            accw[o][t] = make_float2(0.0f, 0.0f);
            accb[o][t] = make_float2(0.0f, 0.0f);
        }

    // double-buffered x registers
    float2 xp[2][TOKPT][2];
    #pragma unroll
    for (int t = 0; t < TOKPT; t++) {
        const float* pt = xT + t * THREADS;
        xp[0][t][0] = make_float2(pt[0],        pt[NTOK]);
        xp[0][t][1] = make_float2(pt[2 * NTOK], pt[3 * NTOK]);
    }

    #pragma unroll 2
    for (int dc = 0; dc < DIM / 4; dc++) {
        const int cur = dc & 1, nxt = cur ^ 1;
        {
            const float* pn = xT + (size_t)(4 * ((dc + 1) & (DIM / 4 - 1))) * NTOK;
            #pragma unroll
            for (int t = 0; t < TOKPT; t++) {
                const float* pt = pn + t * THREADS;
                xp[nxt][t][0] = make_float2(pt[0],        pt[NTOK]);
                xp[nxt][t][1] = make_float2(pt[2 * NTOK], pt[3 * NTOK]);
            }
        }

        #pragma unroll
        for (int o = 0; o < OT; o++) {
            float4 T4 = sT [o][dc];
            float4 A4 = sA [o][dc];
            float4 P4 = sCP[o][dc];
            float4 W4 = sW [o][dc];
            float2 Tl = make_float2(T4.x, T4.y), Th = make_float2(T4.z, T4.w);
            float2 Al = make_float2(A4.x, A4.y), Ah = make_float2(A4.z, A4.w);
            float2 Pl = make_float2(P4.x, P4.y), Ph = make_float2(P4.z, P4.w);
            float2 Wl = make_float2(W4.x, W4.y), Wh = make_float2(W4.z, W4.w);
            #pragma unroll
            for (int t = 0; t < TOKPT; t++) {
                {
                    float2 y = fadd2(xp[cur][t][0], Tl);
                    float2 q = fmul2(y, y);
                    float2 m = ffma2(q, Al, H2);
                    float2 e = make_float2(ex2f(m.x), ex2f(m.y));
                    float2 g = fmul2(m, e);
                    accw[o][t] = ffma2(g, Pl, accw[o][t]);
                }
                {
                    float2 y = fadd2(xp[cur][t][1], Th);
                    float2 q = fmul2(y, y);
                    float2 m = ffma2(q, Ah, H2);
                    float2 e = make_float2(ex2f(m.x), ex2f(m.y));
                    float2 g = fmul2(m, e);
                    accw[o][t] = ffma2(g, Ph, accw[o][t]);
                }
                accb[o][t] = ffma2(xp[cur][t][0], Wl, accb[o][t]);
                accb[o][t] = ffma2(xp[cur][t][1], Wh, accb[o][t]);
            }
        }
    }

    // ---- epilogue ----
    #pragma unroll
    for (int t = 0; t < TOKPT; t++) {
        int n = n0 + t * THREADS;
        float2 ms = g_musv[n];
        float* op = out + (size_t)n * ODIM + o0;
        float4 res;
        float* rp = (float*)&res;
        #pragma unroll
        for (int j = 0; j < 4; j++) {
            float ac = accb[j][t].x + accb[j][t].y;
            float b = fmaf(ms.y, ac - sK1[j], ms.x * sK2[j]);
            float e = ex2f(-1.44269504f * b);
            float sig = __frcp_rn(1.0f + e);
            rp[j] = fmaf(b, sig, accw[j][t].x + accw[j][t].y);
        }
        ((float4*)op)[0] = res;
    }
}

extern "C" void kernel_launch(void* const* d_in, const int* in_sizes, int n_in,
                              void* d_out, int out_size) {
    const float* x     = (const float*)d_in[0];
    const float* scale = (const float*)d_in[1];
    const float* trans = (const float*)d_in[2];
    const float* ww    = (const float*)d_in[3];
    const float* bw    = (const float*)d_in[4];
    const float* gamma = (const float*)d_in[5];
    const float* beta  = (const float*)d_in[6];
    float* out = (float*)d_out;

    ln_kernel<<<NTOK / 8, 256>>>(x, gamma, beta, scale, trans, ww, bw);
    dim3 grid(NTOK / (THREADS * TOKPT), ODIM / OT);
    wave_kernel<<<grid, THREADS>>>(out);
}